// round 1
// baseline (speedup 1.0000x reference)
#include <cuda_runtime.h>
#include <math.h>

#define Bq   128
#define Tq   256
#define Vq   32000
#define Eq   512
#define Hq   1024
#define TOPq 128
#define Fq   512
#define Oq   10
#define G4   4096
#define NH   8      // hidden units per CTA in the recurrence

// ---------------- device scratch (allocation-free; module globals) ----------
__device__ float g_xg[(size_t)Bq * Tq * G4];   // 512 MB: precomputed input+topic gates
__device__ float g_tb[Bq * G4];                // topic bias per (b, gate-col)
__device__ float g_hbuf[2 * Bq * Hq];          // double-buffered hidden state
__device__ float g_c[Bq * Hq];                 // cell state
__device__ float g_h1[Bq * Fq];                // fc1 output
__device__ float g_s[Fq];                      // BN scale  (rstd*gamma)
__device__ float g_t[Fq];                      // BN shift  (beta - mu*rstd*gamma)

typedef unsigned long long u64;

// ---------------- packed f32x2 helpers (Blackwell dual-rate fp32) -----------
__device__ __forceinline__ void fma2(u64 &d, u64 a, u64 b) {
    asm("fma.rn.f32x2 %0, %1, %2, %0;" : "+l"(d) : "l"(a), "l"(b));
}
__device__ __forceinline__ u64 pk2(float lo, float hi) {
    u64 r; asm("mov.b64 %0, {%1, %2};" : "=l"(r) : "f"(lo), "f"(hi)); return r;
}
__device__ __forceinline__ float2 upk2(u64 v) {
    float2 r; asm("mov.b64 {%0, %1}, %2;" : "=f"(r.x), "=f"(r.y) : "l"(v)); return r;
}
__device__ __forceinline__ float sigmoidf(float x) { return 1.0f / (1.0f + expf(-x)); }

// ---------------- init: zero h0, c0 -----------------------------------------
__global__ void k_init() {
    int i = blockIdx.x * blockDim.x + threadIdx.x;
    if (i < Bq * Hq) { g_c[i] = 0.f; g_hbuf[i] = 0.f; }
}

// ---------------- topic bias: tb[b][g] = b[g] + x_top[b] . w_th[g] ----------
__global__ __launch_bounds__(256) void k_topic(const float* __restrict__ x_top,
                                               const float* __restrict__ w_th,
                                               const float* __restrict__ bias) {
    __shared__ float xt[TOPq];
    int b = blockIdx.x, tid = threadIdx.x;
    if (tid < TOPq) xt[tid] = x_top[b * TOPq + tid];
    __syncthreads();
    for (int g = tid; g < G4; g += 256) {
        const float4* wr = (const float4*)(w_th + (size_t)g * TOPq);
        float s = bias[g];
        #pragma unroll
        for (int k = 0; k < TOPq / 4; k++) {
            float4 w4 = wr[k];
            s += xt[4*k]*w4.x + xt[4*k+1]*w4.y + xt[4*k+2]*w4.z + xt[4*k+3]*w4.w;
        }
        g_tb[b * G4 + g] = s;
    }
}

// ---------------- xg GEMM with embedding gather ------------------------------
// xg[m][n] = sum_e emb[x[m]][e] * w_ih[n][e] + tb[m/T][n],  M=32768 N=4096 K=512
// CTA tile 128x64, 256 threads, 8x4 outputs/thread, f32x2 accumulation.
__global__ __launch_bounds__(256) void k_xg(const int* __restrict__ x,
                                            const float* __restrict__ emb,
                                            const float* __restrict__ w_ih) {
    __shared__ float As[16][132];   // [k][m]
    __shared__ float Bs[16][68];    // [k][n]
    __shared__ int rows_s[128];
    int tid = threadIdx.x;
    int n0 = blockIdx.x * 64;
    int m0 = blockIdx.y * 128;
    int bb = m0 >> 8;               // batch index (T=256, tile fits in one b)
    if (tid < 128) rows_s[tid] = x[m0 + tid];
    __syncthreads();

    int rg = tid >> 4, cg = tid & 15;
    u64 acc[8][2];
    #pragma unroll
    for (int r = 0; r < 8; r++) { acc[r][0] = 0ull; acc[r][1] = 0ull; }

    for (int kt = 0; kt < Eq / 16; kt++) {
        #pragma unroll
        for (int i = 0; i < 2; i++) {                 // A: 128x16
            int idx = tid + i * 256;
            int mi = idx >> 2, k4 = idx & 3;
            float4 v = *(const float4*)(emb + (size_t)rows_s[mi] * Eq + kt * 16 + k4 * 4);
            As[k4*4+0][mi] = v.x; As[k4*4+1][mi] = v.y;
            As[k4*4+2][mi] = v.z; As[k4*4+3][mi] = v.w;
        }
        {                                             // B: 64x16
            int nl = tid >> 2, k4 = tid & 3;
            float4 v = *(const float4*)(w_ih + (size_t)(n0 + nl) * Eq + kt * 16 + k4 * 4);
            Bs[k4*4+0][nl] = v.x; Bs[k4*4+1][nl] = v.y;
            Bs[k4*4+2][nl] = v.z; Bs[k4*4+3][nl] = v.w;
        }
        __syncthreads();
        #pragma unroll
        for (int k = 0; k < 16; k++) {
            float4 a0 = *(const float4*)&As[k][rg * 8];
            float4 a1 = *(const float4*)&As[k][rg * 8 + 4];
            float4 b4 = *(const float4*)&Bs[k][cg * 4];
            u64 b20 = pk2(b4.x, b4.y), b21 = pk2(b4.z, b4.w);
            u64 a2[8] = {pk2(a0.x,a0.x), pk2(a0.y,a0.y), pk2(a0.z,a0.z), pk2(a0.w,a0.w),
                         pk2(a1.x,a1.x), pk2(a1.y,a1.y), pk2(a1.z,a1.z), pk2(a1.w,a1.w)};
            #pragma unroll
            for (int r = 0; r < 8; r++) { fma2(acc[r][0], a2[r], b20); fma2(acc[r][1], a2[r], b21); }
        }
        __syncthreads();
    }
    float4 tb4 = *(const float4*)(g_tb + bb * G4 + n0 + cg * 4);
    #pragma unroll
    for (int r = 0; r < 8; r++) {
        int m = m0 + rg * 8 + r;
        float2 f0 = upk2(acc[r][0]), f1 = upk2(acc[r][1]);
        float4 o; o.x = f0.x + tb4.x; o.y = f0.y + tb4.y; o.z = f1.x + tb4.z; o.w = f1.y + tb4.w;
        *(float4*)(g_xg + (size_t)m * G4 + n0 + cg * 4) = o;
    }
}

// ---------------- one LSTM step ----------------------------------------------
// CTA n owns hidden slice [n*8, n*8+8): computes the 32 gate columns
// {g*1024 + n*8 + lh} for all 128 batches, K=1024, then updates c,h locally.
__global__ __launch_bounds__(256) void k_step(const float* __restrict__ w_hh, int t) {
    __shared__ float Hs[32][132];   // [k][b]
    __shared__ float Ws[32][36];    // [k][j]  j = gate*8 + lh (local)
    __shared__ float Gs[128][33];   // gate exchange [b][j]
    int tid = threadIdx.x;
    int n = blockIdx.x;
    const float* hin = g_hbuf + (size_t)(t & 1) * (Bq * Hq);
    float* hout = g_hbuf + (size_t)((t + 1) & 1) * (Bq * Hq);

    int rg = tid >> 3, cg = tid & 7;           // 4 rows x 4 cols per thread
    int jw = tid >> 3, k4w = tid & 7;          // W-load mapping
    int grow = (jw >> 3) * Hq + n * NH + (jw & 7);

    u64 acc[4][2];
    #pragma unroll
    for (int r = 0; r < 4; r++) { acc[r][0] = 0ull; acc[r][1] = 0ull; }

    for (int kt = 0; kt < Hq / 32; kt++) {
        #pragma unroll
        for (int i = 0; i < 4; i++) {             // H tile: 128 b x 32 k
            int idx = tid + i * 256;
            int b = idx >> 3, k4 = idx & 7;
            float4 v = *(const float4*)(hin + (size_t)b * Hq + kt * 32 + k4 * 4);
            Hs[k4*4+0][b] = v.x; Hs[k4*4+1][b] = v.y;
            Hs[k4*4+2][b] = v.z; Hs[k4*4+3][b] = v.w;
        }
        {                                          // W tile: 32 cols x 32 k
            float4 v = *(const float4*)(w_hh + (size_t)grow * Hq + kt * 32 + k4w * 4);
            Ws[k4w*4+0][jw] = v.x; Ws[k4w*4+1][jw] = v.y;
            Ws[k4w*4+2][jw] = v.z; Ws[k4w*4+3][jw] = v.w;
        }
        __syncthreads();
        #pragma unroll
        for (int k = 0; k < 32; k++) {
            float4 a  = *(const float4*)&Hs[k][rg * 4];
            float4 b4 = *(const float4*)&Ws[k][cg * 4];
            u64 b20 = pk2(b4.x, b4.y), b21 = pk2(b4.z, b4.w);
            u64 a2[4] = {pk2(a.x,a.x), pk2(a.y,a.y), pk2(a.z,a.z), pk2(a.w,a.w)};
            #pragma unroll
            for (int r = 0; r < 4; r++) { fma2(acc[r][0], a2[r], b20); fma2(acc[r][1], a2[r], b21); }
        }
        __syncthreads();
    }
    #pragma unroll
    for (int r = 0; r < 4; r++) {
        float2 f0 = upk2(acc[r][0]), f1 = upk2(acc[r][1]);
        Gs[rg*4+r][cg*4+0] = f0.x; Gs[rg*4+r][cg*4+1] = f0.y;
        Gs[rg*4+r][cg*4+2] = f1.x; Gs[rg*4+r][cg*4+3] = f1.y;
    }
    __syncthreads();
    #pragma unroll
    for (int i = 0; i < 4; i++) {
        int it = tid + i * 256;
        int b = it >> 3, lh = it & 7;
        int hg = n * NH + lh;
        const float* xr = g_xg + (size_t)(b * Tq + t) * G4;
        float xi  = Gs[b][lh]        + xr[hg];
        float xf  = Gs[b][8 + lh]    + xr[Hq + hg];
        float xgv = Gs[b][16 + lh]   + xr[2 * Hq + hg];
        float xo  = Gs[b][24 + lh]   + xr[3 * Hq + hg];
        float ii = sigmoidf(xi), ff = sigmoidf(xf), oo = sigmoidf(xo);
        float c = ff * g_c[b * Hq + hg] + ii * tanhf(xgv);
        g_c[b * Hq + hg] = c;
        hout[b * Hq + hg] = oo * tanhf(c);
    }
}

// ---------------- fc1: h1 = h_T @ fc1_w.T + fc1_b ---------------------------
__global__ __launch_bounds__(256) void k_fc1(const float* __restrict__ fc1_w,
                                             const float* __restrict__ fc1_b) {
    int b = blockIdx.y;
    int f = blockIdx.x * 8 + (threadIdx.x >> 5);
    int lane = threadIdx.x & 31;
    const float* hr = g_hbuf + (size_t)b * Hq;     // final h lands in buffer 0 (T even)
    const float* wr = fc1_w + (size_t)f * Hq;
    float s = 0.f;
    for (int k = lane; k < Hq; k += 32) s += hr[k] * wr[k];
    #pragma unroll
    for (int off = 16; off; off >>= 1) s += __shfl_xor_sync(0xffffffffu, s, off);
    if (lane == 0) g_h1[b * Fq + f] = s + fc1_b[f];
}

// ---------------- BN stats (training-mode batch statistics) -----------------
__global__ void k_bn(const float* __restrict__ gamma, const float* __restrict__ beta) {
    int f = threadIdx.x;
    float s = 0.f, ss = 0.f;
    for (int b = 0; b < Bq; b++) { float v = g_h1[b * Fq + f]; s += v; ss += v * v; }
    float mu = s * (1.f / Bq);
    float var = ss * (1.f / Bq) - mu * mu;
    float rstd = rsqrtf(var + 1e-5f);
    float sc = rstd * gamma[f];
    g_s[f] = sc;
    g_t[f] = beta[f] - mu * sc;
}

// ---------------- fc2 on normalized h1 --------------------------------------
__global__ __launch_bounds__(320) void k_out(const float* __restrict__ fc2_w,
                                             const float* __restrict__ fc2_b,
                                             float* __restrict__ out) {
    int b = blockIdx.x;
    int o = threadIdx.x >> 5;     // 10 warps
    int lane = threadIdx.x & 31;
    const float* h1r = g_h1 + (size_t)b * Fq;
    const float* wr = fc2_w + (size_t)o * Fq;
    float s = 0.f;
    for (int f = lane; f < Fq; f += 32) s += (h1r[f] * g_s[f] + g_t[f]) * wr[f];
    #pragma unroll
    for (int off = 16; off; off >>= 1) s += __shfl_xor_sync(0xffffffffu, s, off);
    if (lane == 0) out[b * Oq + o] = s + fc2_b[o];
}

// ---------------- launch ------------------------------------------------------
extern "C" void kernel_launch(void* const* d_in, const int* in_sizes, int n_in,
                              void* d_out, int out_size) {
    const int*   x     = (const int*)  d_in[0];
    const float* x_top = (const float*)d_in[1];
    const float* emb   = (const float*)d_in[2];
    const float* w_ih  = (const float*)d_in[3];
    const float* w_hh  = (const float*)d_in[4];
    const float* w_th  = (const float*)d_in[5];
    const float* bias  = (const float*)d_in[6];
    const float* fc1_w = (const float*)d_in[7];
    const float* fc1_b = (const float*)d_in[8];
    const float* gamma = (const float*)d_in[9];
    const float* beta  = (const float*)d_in[10];
    const float* fc2_w = (const float*)d_in[11];
    const float* fc2_b = (const float*)d_in[12];
    float* out = (float*)d_out;

    k_init<<<(Bq * Hq + 255) / 256, 256>>>();
    k_topic<<<Bq, 256>>>(x_top, w_th, bias);
    dim3 gxg(G4 / 64, (Bq * Tq) / 128);
    k_xg<<<gxg, 256>>>(x, emb, w_ih);
    for (int t = 0; t < Tq; t++)
        k_step<<<Hq / NH, 256>>>(w_hh, t);
    k_fc1<<<dim3(Fq / 8, Bq), 256>>>(fc1_w, fc1_b);
    k_bn<<<1, Fq>>>(gamma, beta);
    k_out<<<Bq, 320>>>(fc2_w, fc2_b, out);
}

// round 3
// speedup vs baseline: 1.9668x; 1.9668x over previous
#include <cuda_runtime.h>
#include <cuda_bf16.h>
#include <math.h>
#include <cstdint>

#define Bq   128
#define Tq   256
#define Eq   512
#define Hq   1024
#define TOPq 128
#define Fq   512
#define Oq   10
#define G4   4096
#define NH   8

typedef unsigned long long u64;
typedef unsigned int u32;

// ---------------- device scratch ----------------
__device__ float g_xg[(size_t)Bq * Tq * G4];
__device__ float g_tb[Bq * G4];
__device__ float g_hbuf[2 * Bq * Hq];               // fp32 hidden (for fc1)
__device__ float g_c[Bq * Hq];
__device__ __nv_bfloat16 g_hhi[2 * Bq * Hq];
__device__ __nv_bfloat16 g_hlo[2 * Bq * Hq];
__device__ __nv_bfloat16 g_whi[(size_t)G4 * Hq];
__device__ __nv_bfloat16 g_wlo[(size_t)G4 * Hq];
__device__ float g_h1[Bq * Fq];
__device__ float g_s[Fq];
__device__ float g_t[Fq];

// ---------------- helpers ----------------
__device__ __forceinline__ void fma2(u64 &d, u64 a, u64 b) {
    asm("fma.rn.f32x2 %0, %1, %2, %0;" : "+l"(d) : "l"(a), "l"(b));
}
__device__ __forceinline__ u64 pk2(float lo, float hi) {
    u64 r; asm("mov.b64 %0, {%1, %2};" : "=l"(r) : "f"(lo), "f"(hi)); return r;
}
__device__ __forceinline__ float2 upk2(u64 v) {
    float2 r; asm("mov.b64 {%0, %1}, %2;" : "=f"(r.x), "=f"(r.y) : "l"(v)); return r;
}
__device__ __forceinline__ float sigmoidf(float x) { return 1.0f / (1.0f + expf(-x)); }

__device__ __forceinline__ u32 smem_u32(const void* p) {
    u32 a; asm("{ .reg .u64 t; cvta.to.shared.u64 t, %1; cvt.u32.u64 %0, t; }" : "=r"(a) : "l"(p));
    return a;
}
__device__ __forceinline__ void ldm4(u32 &r0, u32 &r1, u32 &r2, u32 &r3, u32 addr) {
    asm volatile("ldmatrix.sync.aligned.m8n8.x4.shared.b16 {%0,%1,%2,%3}, [%4];"
        : "=r"(r0), "=r"(r1), "=r"(r2), "=r"(r3) : "r"(addr));
}
__device__ __forceinline__ void mma16816(float* d, const u32* a, u32 b0, u32 b1) {
    asm volatile("mma.sync.aligned.m16n8k16.row.col.f32.bf16.bf16.f32 "
        "{%0,%1,%2,%3}, {%4,%5,%6,%7}, {%8,%9}, {%0,%1,%2,%3};"
        : "+f"(d[0]), "+f"(d[1]), "+f"(d[2]), "+f"(d[3])
        : "r"(a[0]), "r"(a[1]), "r"(a[2]), "r"(a[3]), "r"(b0), "r"(b1));
}

// ---------------- init ----------------
__global__ void k_init() {
    int i = blockIdx.x * blockDim.x + threadIdx.x;
    if (i < Bq * Hq) {
        g_c[i] = 0.f; g_hbuf[i] = 0.f;
        g_hhi[i] = __float2bfloat16(0.f);
        g_hlo[i] = __float2bfloat16(0.f);
    }
}

// ---------------- split w_hh into bf16 hi/lo ----------------
__global__ __launch_bounds__(256) void k_wsplit(const float* __restrict__ w) {
    size_t i = ((size_t)blockIdx.x * 256 + threadIdx.x) * 4;
    float4 v = *(const float4*)(w + i);
    float vv[4] = {v.x, v.y, v.z, v.w};
    __nv_bfloat16 hi[4], lo[4];
    #pragma unroll
    for (int j = 0; j < 4; j++) {
        hi[j] = __float2bfloat16(vv[j]);
        lo[j] = __float2bfloat16(vv[j] - __bfloat162float(hi[j]));
    }
    *(uint2*)(g_whi + i) = *(uint2*)hi;
    *(uint2*)(g_wlo + i) = *(uint2*)lo;
}

// ---------------- topic bias ----------------
__global__ __launch_bounds__(256) void k_topic(const float* __restrict__ x_top,
                                               const float* __restrict__ w_th,
                                               const float* __restrict__ bias) {
    __shared__ float xt[TOPq];
    int b = blockIdx.x, tid = threadIdx.x;
    if (tid < TOPq) xt[tid] = x_top[b * TOPq + tid];
    __syncthreads();
    for (int g = tid; g < G4; g += 256) {
        const float4* wr = (const float4*)(w_th + (size_t)g * TOPq);
        float s = bias[g];
        #pragma unroll
        for (int k = 0; k < TOPq / 4; k++) {
            float4 w4 = wr[k];
            s += xt[4*k]*w4.x + xt[4*k+1]*w4.y + xt[4*k+2]*w4.z + xt[4*k+3]*w4.w;
        }
        g_tb[b * G4 + g] = s;
    }
}

// ---------------- xg GEMM (fp32 SIMT, unchanged) ----------------
__global__ __launch_bounds__(256) void k_xg(const int* __restrict__ x,
                                            const float* __restrict__ emb,
                                            const float* __restrict__ w_ih) {
    __shared__ float As[16][132];
    __shared__ float Bs[16][68];
    __shared__ int rows_s[128];
    int tid = threadIdx.x;
    int n0 = blockIdx.x * 64;
    int m0 = blockIdx.y * 128;
    int bb = m0 >> 8;
    if (tid < 128) rows_s[tid] = x[m0 + tid];
    __syncthreads();

    int rg = tid >> 4, cg = tid & 15;
    u64 acc[8][2];
    #pragma unroll
    for (int r = 0; r < 8; r++) { acc[r][0] = 0ull; acc[r][1] = 0ull; }

    for (int kt = 0; kt < Eq / 16; kt++) {
        #pragma unroll
        for (int i = 0; i < 2; i++) {
            int idx = tid + i * 256;
            int mi = idx >> 2, k4 = idx & 3;
            float4 v = *(const float4*)(emb + (size_t)rows_s[mi] * Eq + kt * 16 + k4 * 4);
            As[k4*4+0][mi] = v.x; As[k4*4+1][mi] = v.y;
            As[k4*4+2][mi] = v.z; As[k4*4+3][mi] = v.w;
        }
        {
            int nl = tid >> 2, k4 = tid & 3;
            float4 v = *(const float4*)(w_ih + (size_t)(n0 + nl) * Eq + kt * 16 + k4 * 4);
            Bs[k4*4+0][nl] = v.x; Bs[k4*4+1][nl] = v.y;
            Bs[k4*4+2][nl] = v.z; Bs[k4*4+3][nl] = v.w;
        }
        __syncthreads();
        #pragma unroll
        for (int k = 0; k < 16; k++) {
            float4 a0 = *(const float4*)&As[k][rg * 8];
            float4 a1 = *(const float4*)&As[k][rg * 8 + 4];
            float4 b4 = *(const float4*)&Bs[k][cg * 4];
            u64 b20 = pk2(b4.x, b4.y), b21 = pk2(b4.z, b4.w);
            u64 a2[8] = {pk2(a0.x,a0.x), pk2(a0.y,a0.y), pk2(a0.z,a0.z), pk2(a0.w,a0.w),
                         pk2(a1.x,a1.x), pk2(a1.y,a1.y), pk2(a1.z,a1.z), pk2(a1.w,a1.w)};
            #pragma unroll
            for (int r = 0; r < 8; r++) { fma2(acc[r][0], a2[r], b20); fma2(acc[r][1], a2[r], b21); }
        }
        __syncthreads();
    }
    float4 tb4 = *(const float4*)(g_tb + bb * G4 + n0 + cg * 4);
    #pragma unroll
    for (int r = 0; r < 8; r++) {
        int m = m0 + rg * 8 + r;
        float2 f0 = upk2(acc[r][0]), f1 = upk2(acc[r][1]);
        float4 o; o.x = f0.x + tb4.x; o.y = f0.y + tb4.y; o.z = f1.x + tb4.z; o.w = f1.y + tb4.w;
        *(float4*)(g_xg + (size_t)m * G4 + n0 + cg * 4) = o;
    }
}

// ---------------- LSTM step: mma.sync bf16 split-2 ----------------
// CTA n owns hidden units [n*8, n*8+8) -> 32 gate cols. D[128 b, 32 cols],
// K=1024 in 16 chunks of 64, double-buffered smem, 8 warps (16 rows each).
// Smem byte layout (dynamic, 92160 B):
//  A(buf,half): (buf*2+half)*18432           (128 rows x 72 bf16, stride 144B)
//  B(buf,half): 73728 + (buf*2+half)*4608    (32 rows x 72 bf16)
#define A_STRIDE 144
#define A_HALF   18432
#define B_BASE   73728
#define B_HALF   4608
#define STEP_SMEM 92160

__global__ __launch_bounds__(256) void k_step(int t) {
    extern __shared__ char dsm[];
    int tid = threadIdx.x, wid = tid >> 5, lane = tid & 31;
    int n = blockIdx.x;

    const __nv_bfloat16* hh = g_hhi + (size_t)(t & 1) * (Bq * Hq);
    const __nv_bfloat16* hl = g_hlo + (size_t)(t & 1) * (Bq * Hq);

    // gmem load mapping
    int arow[4], ac[4];
    #pragma unroll
    for (int i = 0; i < 4; i++) {
        int u = tid + i * 256;
        arow[i] = u >> 3; ac[i] = u & 7;
    }
    int brow = tid >> 3, bc = tid & 7;
    size_t bg = (size_t)((brow >> 3) * Hq + n * NH + (brow & 7)) * Hq + bc * 8;

    // ldmatrix lane addresses (byte)
    u32 sb = smem_u32(dsm);
    int amrow = wid * 16 + (lane & 7) + ((lane >> 3) & 1) * 8;
    u32 aAddr = sb + amrow * A_STRIDE + (lane >> 4) * 16;
    u32 bAddr = sb + B_BASE + lane * A_STRIDE;

    float acc[4][4];
    #pragma unroll
    for (int i = 0; i < 4; i++) { acc[i][0]=0.f; acc[i][1]=0.f; acc[i][2]=0.f; acc[i][3]=0.f; }

    // prefetch chunk 0
    uint4 pA[8], pB[2];
    #pragma unroll
    for (int i = 0; i < 4; i++) {
        size_t off = (size_t)arow[i] * Hq + ac[i] * 8;
        pA[i]     = *(const uint4*)(hh + off);
        pA[4 + i] = *(const uint4*)(hl + off);
    }
    pB[0] = *(const uint4*)(g_whi + bg);
    pB[1] = *(const uint4*)(g_wlo + bg);

    for (int c = 0; c < 16; c++) {
        int buf = c & 1;
        char* aH = dsm + buf * (2 * A_HALF);
        char* aL = aH + A_HALF;
        char* bH = dsm + B_BASE + buf * (2 * B_HALF);
        char* bL = bH + B_HALF;
        #pragma unroll
        for (int i = 0; i < 4; i++) {
            int so = arow[i] * A_STRIDE + ac[i] * 16;
            *(uint4*)(aH + so) = pA[i];
            *(uint4*)(aL + so) = pA[4 + i];
        }
        {
            int so = brow * A_STRIDE + bc * 16;
            *(uint4*)(bH + so) = pB[0];
            *(uint4*)(bL + so) = pB[1];
        }
        if (c < 15) {
            int k0 = (c + 1) * 64;
            #pragma unroll
            for (int i = 0; i < 4; i++) {
                size_t off = (size_t)arow[i] * Hq + k0 + ac[i] * 8;
                pA[i]     = *(const uint4*)(hh + off);
                pA[4 + i] = *(const uint4*)(hl + off);
            }
            pB[0] = *(const uint4*)(g_whi + bg + k0);
            pB[1] = *(const uint4*)(g_wlo + bg + k0);
        }
        __syncthreads();

        u32 oAh = buf * (2 * A_HALF);
        u32 oAl = oAh + A_HALF;
        u32 oBh = buf * (2 * B_HALF);
        u32 oBl = oBh + B_HALF;
        #pragma unroll
        for (int s = 0; s < 4; s++) {
            u32 ah[4], al[4], bh0[4], bh1[4], bl0[4], bl1[4];
            ldm4(ah[0], ah[1], ah[2], ah[3], aAddr + oAh + s * 32);
            ldm4(al[0], al[1], al[2], al[3], aAddr + oAl + s * 32);
            ldm4(bh0[0], bh0[1], bh0[2], bh0[3], bAddr + oBh + s * 32);
            ldm4(bh1[0], bh1[1], bh1[2], bh1[3], bAddr + oBh + s * 32 + 16);
            ldm4(bl0[0], bl0[1], bl0[2], bl0[3], bAddr + oBl + s * 32);
            ldm4(bl1[0], bl1[1], bl1[2], bl1[3], bAddr + oBl + s * 32 + 16);
            #pragma unroll
            for (int nt = 0; nt < 4; nt++) {
                mma16816(acc[nt], ah, bh0[nt], bh1[nt]);
                mma16816(acc[nt], ah, bl0[nt], bl1[nt]);
                mma16816(acc[nt], al, bh0[nt], bh1[nt]);
            }
        }
        __syncthreads();
    }

    // ---- epilogue: fully in registers ----
    // thread holds rows {w*16+g, +8}, units {2t, 2t+1}, gate nt: acc[nt][rr*2+du]
    int g = lane >> 2, tq = lane & 3;
    int u0 = tq * 2;
    #pragma unroll
    for (int rr = 0; rr < 2; rr++) {
        int b = wid * 16 + g + rr * 8;
        const float* xr = g_xg + ((size_t)b * Tq + t) * G4 + n * NH + u0;
        float2 x0 = *(const float2*)(xr);
        float2 x1 = *(const float2*)(xr + Hq);
        float2 x2 = *(const float2*)(xr + 2 * Hq);
        float2 x3 = *(const float2*)(xr + 3 * Hq);
        float* cp = g_c + (size_t)b * Hq + n * NH + u0;
        float2 cold = *(float2*)cp;

        float i0 = sigmoidf(acc[0][rr*2+0] + x0.x);
        float f0 = sigmoidf(acc[1][rr*2+0] + x1.x);
        float gg0 = tanhf(acc[2][rr*2+0] + x2.x);
        float o0 = sigmoidf(acc[3][rr*2+0] + x3.x);
        float i1 = sigmoidf(acc[0][rr*2+1] + x0.y);
        float f1 = sigmoidf(acc[1][rr*2+1] + x1.y);
        float gg1 = tanhf(acc[2][rr*2+1] + x2.y);
        float o1 = sigmoidf(acc[3][rr*2+1] + x3.y);

        float2 cv, hv;
        cv.x = f0 * cold.x + i0 * gg0;
        cv.y = f1 * cold.y + i1 * gg1;
        hv.x = o0 * tanhf(cv.x);
        hv.y = o1 * tanhf(cv.y);
        *(float2*)cp = cv;

        size_t hob = (size_t)((t + 1) & 1) * (Bq * Hq) + (size_t)b * Hq + n * NH + u0;
        *(float2*)(g_hbuf + hob) = hv;

        __nv_bfloat162 hi2, lo2;
        hi2.x = __float2bfloat16(hv.x);
        hi2.y = __float2bfloat16(hv.y);
        lo2.x = __float2bfloat16(hv.x - __bfloat162float(hi2.x));
        lo2.y = __float2bfloat16(hv.y - __bfloat162float(hi2.y));
        *(__nv_bfloat162*)(g_hhi + hob) = hi2;
        *(__nv_bfloat162*)(g_hlo + hob) = lo2;
    }
}

// ---------------- fc1 ----------------
__global__ __launch_bounds__(256) void k_fc1(const float* __restrict__ fc1_w,
                                             const float* __restrict__ fc1_b) {
    int b = blockIdx.y;
    int f = blockIdx.x * 8 + (threadIdx.x >> 5);
    int lane = threadIdx.x & 31;
    const float* hr = g_hbuf + (size_t)b * Hq;   // final h in buffer 0 (T even)
    const float* wr = fc1_w + (size_t)f * Hq;
    float s = 0.f;
    for (int k = lane; k < Hq; k += 32) s += hr[k] * wr[k];
    #pragma unroll
    for (int off = 16; off; off >>= 1) s += __shfl_xor_sync(0xffffffffu, s, off);
    if (lane == 0) g_h1[b * Fq + f] = s + fc1_b[f];
}

// ---------------- BN stats ----------------
__global__ void k_bn(const float* __restrict__ gamma, const float* __restrict__ beta) {
    int f = threadIdx.x;
    float s = 0.f, ss = 0.f;
    for (int b = 0; b < Bq; b++) { float v = g_h1[b * Fq + f]; s += v; ss += v * v; }
    float mu = s * (1.f / Bq);
    float var = ss * (1.f / Bq) - mu * mu;
    float rstd = rsqrtf(var + 1e-5f);
    float sc = rstd * gamma[f];
    g_s[f] = sc;
    g_t[f] = beta[f] - mu * sc;
}

// ---------------- fc2 ----------------
__global__ __launch_bounds__(320) void k_out(const float* __restrict__ fc2_w,
                                             const float* __restrict__ fc2_b,
                                             float* __restrict__ out) {
    int b = blockIdx.x;
    int o = threadIdx.x >> 5;
    int lane = threadIdx.x & 31;
    const float* h1r = g_h1 + (size_t)b * Fq;
    const float* wr = fc2_w + (size_t)o * Fq;
    float s = 0.f;
    for (int f = lane; f < Fq; f += 32) s += (h1r[f] * g_s[f] + g_t[f]) * wr[f];
    #pragma unroll
    for (int off = 16; off; off >>= 1) s += __shfl_xor_sync(0xffffffffu, s, off);
    if (lane == 0) out[b * Oq + o] = s + fc2_b[o];
}

// ---------------- launch ----------------
extern "C" void kernel_launch(void* const* d_in, const int* in_sizes, int n_in,
                              void* d_out, int out_size) {
    const int*   x     = (const int*)  d_in[0];
    const float* x_top = (const float*)d_in[1];
    const float* emb   = (const float*)d_in[2];
    const float* w_ih  = (const float*)d_in[3];
    const float* w_hh  = (const float*)d_in[4];
    const float* w_th  = (const float*)d_in[5];
    const float* bias  = (const float*)d_in[6];
    const float* fc1_w = (const float*)d_in[7];
    const float* fc1_b = (const float*)d_in[8];
    const float* gamma = (const float*)d_in[9];
    const float* beta  = (const float*)d_in[10];
    const float* fc2_w = (const float*)d_in[11];
    const float* fc2_b = (const float*)d_in[12];
    float* out = (float*)d_out;

    cudaFuncSetAttribute(k_step, cudaFuncAttributeMaxDynamicSharedMemorySize, STEP_SMEM);

    k_init<<<(Bq * Hq + 255) / 256, 256>>>();
    k_wsplit<<<(G4 * Hq / 4) / 256, 256>>>(w_hh);
    k_topic<<<Bq, 256>>>(x_top, w_th, bias);
    dim3 gxg(G4 / 64, (Bq * Tq) / 128);
    k_xg<<<gxg, 256>>>(x, emb, w_ih);
    for (int t = 0; t < Tq; t++)
        k_step<<<Hq / NH, 256, STEP_SMEM>>>(t);
    k_fc1<<<dim3(Fq / 8, Bq), 256>>>(fc1_w, fc1_b);
    k_bn<<<1, Fq>>>(gamma, beta);
    k_out<<<Bq, 320>>>(fc2_w, fc2_b, out);
}

// round 4
// speedup vs baseline: 2.5602x; 1.3017x over previous
#include <cuda_runtime.h>
#include <cuda_bf16.h>
#include <math.h>
#include <cstdint>

#define Bq   128
#define Tq   256
#define Eq   512
#define Hq   1024
#define TOPq 128
#define Fq   512
#define Oq   10
#define G4   4096
#define NH   8

typedef unsigned long long u64;
typedef unsigned int u32;

// ---------------- device scratch ----------------
__device__ float g_xg[(size_t)Bq * Tq * G4];
__device__ float g_tb[Bq * G4];
__device__ float g_hbuf[Bq * Hq];                   // final h only (for fc1)
__device__ __nv_bfloat16 g_hhi[2 * Bq * Hq];
__device__ __nv_bfloat16 g_hlo[2 * Bq * Hq];
__device__ __nv_bfloat16 g_whi[(size_t)G4 * Hq];
__device__ __nv_bfloat16 g_wlo[(size_t)G4 * Hq];
__device__ __nv_bfloat16 g_xeb[(size_t)Bq * Tq * Eq];  // gathered emb, bf16
__device__ __nv_bfloat16 g_wihb[(size_t)G4 * Eq];      // w_ih, bf16
__device__ float g_h1[Bq * Fq];
__device__ float g_s[Fq];
__device__ float g_t[Fq];
__device__ unsigned int g_bar;

// ---------------- helpers ----------------
__device__ __forceinline__ float sigmoidf(float x) { return 1.0f / (1.0f + expf(-x)); }

__device__ __forceinline__ u32 smem_u32(const void* p) {
    u32 a; asm("{ .reg .u64 t; cvta.to.shared.u64 t, %1; cvt.u32.u64 %0, t; }" : "=r"(a) : "l"(p));
    return a;
}
__device__ __forceinline__ void ldm4(u32 &r0, u32 &r1, u32 &r2, u32 &r3, u32 addr) {
    asm volatile("ldmatrix.sync.aligned.m8n8.x4.shared.b16 {%0,%1,%2,%3}, [%4];"
        : "=r"(r0), "=r"(r1), "=r"(r2), "=r"(r3) : "r"(addr));
}
__device__ __forceinline__ void mma16816(float* d, const u32* a, u32 b0, u32 b1) {
    asm volatile("mma.sync.aligned.m16n8k16.row.col.f32.bf16.bf16.f32 "
        "{%0,%1,%2,%3}, {%4,%5,%6,%7}, {%8,%9}, {%0,%1,%2,%3};"
        : "+f"(d[0]), "+f"(d[1]), "+f"(d[2]), "+f"(d[3])
        : "r"(a[0]), "r"(a[1]), "r"(a[2]), "r"(a[3]), "r"(b0), "r"(b1));
}

// ---------------- init ----------------
__global__ void k_init() {
    int i = blockIdx.x * blockDim.x + threadIdx.x;
    if (i == 0) g_bar = 0u;
    if (i < Bq * Hq) {
        g_hhi[i] = __float2bfloat16(0.f);
        g_hlo[i] = __float2bfloat16(0.f);
    }
}

// ---------------- split w_hh into bf16 hi/lo ----------------
__global__ __launch_bounds__(256) void k_wsplit(const float* __restrict__ w) {
    size_t i = ((size_t)blockIdx.x * 256 + threadIdx.x) * 4;
    float4 v = *(const float4*)(w + i);
    float vv[4] = {v.x, v.y, v.z, v.w};
    __nv_bfloat16 hi[4], lo[4];
    #pragma unroll
    for (int j = 0; j < 4; j++) {
        hi[j] = __float2bfloat16(vv[j]);
        lo[j] = __float2bfloat16(vv[j] - __bfloat162float(hi[j]));
    }
    *(uint2*)(g_whi + i) = *(uint2*)hi;
    *(uint2*)(g_wlo + i) = *(uint2*)lo;
}

// ---------------- w_ih -> bf16 ----------------
__global__ __launch_bounds__(256) void k_wihb(const float* __restrict__ w) {
    size_t i = ((size_t)blockIdx.x * 256 + threadIdx.x) * 4;
    float4 v = *(const float4*)(w + i);
    __nv_bfloat16 b[4] = {__float2bfloat16(v.x), __float2bfloat16(v.y),
                          __float2bfloat16(v.z), __float2bfloat16(v.w)};
    *(uint2*)(g_wihb + i) = *(uint2*)b;
}

// ---------------- emb gather -> bf16 ----------------
__global__ __launch_bounds__(256) void k_xeb(const int* __restrict__ x,
                                             const float* __restrict__ emb) {
    size_t idx = (size_t)blockIdx.x * 256 + threadIdx.x;   // one per 4 elems
    int m = (int)(idx >> 7);            // Eq/4 = 128 quads per row
    int e4 = ((int)idx & 127) * 4;
    int row = x[m];
    float4 v = *(const float4*)(emb + (size_t)row * Eq + e4);
    __nv_bfloat16 b[4] = {__float2bfloat16(v.x), __float2bfloat16(v.y),
                          __float2bfloat16(v.z), __float2bfloat16(v.w)};
    *(uint2*)(g_xeb + (size_t)m * Eq + e4) = *(uint2*)b;
}

// ---------------- topic bias ----------------
__global__ __launch_bounds__(256) void k_topic(const float* __restrict__ x_top,
                                               const float* __restrict__ w_th,
                                               const float* __restrict__ bias) {
    __shared__ float xt[TOPq];
    int b = blockIdx.x, tid = threadIdx.x;
    if (tid < TOPq) xt[tid] = x_top[b * TOPq + tid];
    __syncthreads();
    for (int g = tid; g < G4; g += 256) {
        const float4* wr = (const float4*)(w_th + (size_t)g * TOPq);
        float s = bias[g];
        #pragma unroll
        for (int k = 0; k < TOPq / 4; k++) {
            float4 w4 = wr[k];
            s += xt[4*k]*w4.x + xt[4*k+1]*w4.y + xt[4*k+2]*w4.z + xt[4*k+3]*w4.w;
        }
        g_tb[b * G4 + g] = s;
    }
}

// ---------------- xg GEMM: single-pass bf16 tensor ----------------
// D[m][n] = xe[m] . w_ih[n] + tb[m>>8][n];  M=32768, N=4096, K=512.
// CTA tile 128x64, K-chunks of 64, double-buffered. 8 warps x (16 rows, 64 cols).
#define XA_STRIDE 144
#define XA_HALF   18432
#define XB_BASE   36864
#define XB_HALF   9216
#define XG_SMEM   55296

__global__ __launch_bounds__(256) void k_xg_t() {
    extern __shared__ char dsm[];
    int tid = threadIdx.x, wid = tid >> 5, lane = tid & 31;
    int n0 = blockIdx.x * 64;
    int m0 = blockIdx.y * 128;

    int arow[4], ac[4];
    #pragma unroll
    for (int i = 0; i < 4; i++) { int u = tid + i * 256; arow[i] = u >> 3; ac[i] = u & 7; }
    int brow[2], bc[2];
    #pragma unroll
    for (int i = 0; i < 2; i++) { int u = tid + i * 256; brow[i] = u >> 3; bc[i] = u & 7; }

    u32 sb = smem_u32(dsm);
    int amrow = wid * 16 + (lane & 7) + ((lane >> 3) & 1) * 8;
    u32 aAddr = sb + amrow * XA_STRIDE + (lane >> 4) * 16;
    u32 bAddr = sb + XB_BASE + lane * XA_STRIDE;

    float acc[8][4];
    #pragma unroll
    for (int i = 0; i < 8; i++) { acc[i][0]=0.f; acc[i][1]=0.f; acc[i][2]=0.f; acc[i][3]=0.f; }

    const __nv_bfloat16* Ag = g_xeb + (size_t)m0 * Eq;
    const __nv_bfloat16* Bg = g_wihb + (size_t)n0 * Eq;

    uint4 pA[4], pB[2];
    #pragma unroll
    for (int i = 0; i < 4; i++) pA[i] = *(const uint4*)(Ag + (size_t)arow[i] * Eq + ac[i] * 8);
    #pragma unroll
    for (int i = 0; i < 2; i++) pB[i] = *(const uint4*)(Bg + (size_t)brow[i] * Eq + bc[i] * 8);

    for (int c = 0; c < 8; c++) {
        int buf = c & 1;
        char* aS = dsm + buf * XA_HALF;
        char* bS = dsm + XB_BASE + buf * XB_HALF;
        #pragma unroll
        for (int i = 0; i < 4; i++) *(uint4*)(aS + arow[i] * XA_STRIDE + ac[i] * 16) = pA[i];
        #pragma unroll
        for (int i = 0; i < 2; i++) *(uint4*)(bS + brow[i] * XA_STRIDE + bc[i] * 16) = pB[i];
        if (c < 7) {
            int k0 = (c + 1) * 64;
            #pragma unroll
            for (int i = 0; i < 4; i++) pA[i] = *(const uint4*)(Ag + (size_t)arow[i] * Eq + k0 + ac[i] * 8);
            #pragma unroll
            for (int i = 0; i < 2; i++) pB[i] = *(const uint4*)(Bg + (size_t)brow[i] * Eq + k0 + bc[i] * 8);
        }
        __syncthreads();

        u32 oA = buf * XA_HALF, oB = buf * XB_HALF;
        #pragma unroll
        for (int s = 0; s < 4; s++) {
            u32 a[4], b0[4], b1[4], b2[4], b3[4];
            ldm4(a[0], a[1], a[2], a[3], aAddr + oA + s * 32);
            ldm4(b0[0], b0[1], b0[2], b0[3], bAddr + oB + s * 32);
            ldm4(b1[0], b1[1], b1[2], b1[3], bAddr + oB + s * 32 + 16);
            ldm4(b2[0], b2[1], b2[2], b2[3], bAddr + 4608 + oB + s * 32);
            ldm4(b3[0], b3[1], b3[2], b3[3], bAddr + 4608 + oB + s * 32 + 16);
            #pragma unroll
            for (int nt = 0; nt < 4; nt++) mma16816(acc[nt], a, b0[nt], b1[nt]);
            #pragma unroll
            for (int nt = 0; nt < 4; nt++) mma16816(acc[4 + nt], a, b2[nt], b3[nt]);
        }
        __syncthreads();
    }

    int g = lane >> 2, tq = lane & 3;
    int bb = m0 >> 8;
    const float* tbr = g_tb + (size_t)bb * G4 + n0;
    #pragma unroll
    for (int rr = 0; rr < 2; rr++) {
        int m = m0 + wid * 16 + g + rr * 8;
        float* orow = g_xg + (size_t)m * G4 + n0;
        #pragma unroll
        for (int nt = 0; nt < 8; nt++) {
            int nn = nt * 8 + tq * 2;
            float2 tb2 = *(const float2*)(tbr + nn);
            float2 o;
            o.x = acc[nt][rr * 2 + 0] + tb2.x;
            o.y = acc[nt][rr * 2 + 1] + tb2.y;
            *(float2*)(orow + nn) = o;
        }
    }
}

// ---------------- persistent LSTM recurrence ----------------
// 128 CTAs (one per hidden slice of 8 units -> 32 gate cols), all co-resident.
// Per step: 3-pass bf16 split-2 MMA over K=1024 (16 chunks), register-resident c,
// gmem spin barrier between steps. h via L2 (.cg); w_hh slice L1-resident.
#define A_STRIDE 144
#define A_HALF   18432
#define B_BASE   73728
#define B_HALF   4608
#define STEP_SMEM 92160

__global__ __launch_bounds__(256) void k_rnn() {
    extern __shared__ char dsm[];
    int tid = threadIdx.x, wid = tid >> 5, lane = tid & 31;
    int n = blockIdx.x;

    int arow[4], ac[4];
    #pragma unroll
    for (int i = 0; i < 4; i++) { int u = tid + i * 256; arow[i] = u >> 3; ac[i] = u & 7; }
    int brow = tid >> 3, bc = tid & 7;
    size_t bg = (size_t)((brow >> 3) * Hq + n * NH + (brow & 7)) * Hq + bc * 8;

    u32 sb = smem_u32(dsm);
    int amrow = wid * 16 + (lane & 7) + ((lane >> 3) & 1) * 8;
    u32 aAddr = sb + amrow * A_STRIDE + (lane >> 4) * 16;
    u32 bAddr = sb + B_BASE + lane * A_STRIDE;

    int g = lane >> 2, tq = lane & 3;
    int u0 = tq * 2;
    float creg[4] = {0.f, 0.f, 0.f, 0.f};   // [rr*2 + du]

    for (int t = 0; t < Tq; t++) {
        const __nv_bfloat16* hh = g_hhi + (size_t)(t & 1) * (Bq * Hq);
        const __nv_bfloat16* hl = g_hlo + (size_t)(t & 1) * (Bq * Hq);

        float acc[4][4];
        #pragma unroll
        for (int i = 0; i < 4; i++) { acc[i][0]=0.f; acc[i][1]=0.f; acc[i][2]=0.f; acc[i][3]=0.f; }

        uint4 pA[8], pB[2];
        #pragma unroll
        for (int i = 0; i < 4; i++) {
            size_t off = (size_t)arow[i] * Hq + ac[i] * 8;
            pA[i]     = __ldcg((const uint4*)(hh + off));
            pA[4 + i] = __ldcg((const uint4*)(hl + off));
        }
        pB[0] = *(const uint4*)(g_whi + bg);
        pB[1] = *(const uint4*)(g_wlo + bg);

        for (int c = 0; c < 16; c++) {
            int buf = c & 1;
            char* aH = dsm + buf * (2 * A_HALF);
            char* aL = aH + A_HALF;
            char* bH = dsm + B_BASE + buf * (2 * B_HALF);
            char* bL = bH + B_HALF;
            #pragma unroll
            for (int i = 0; i < 4; i++) {
                int so = arow[i] * A_STRIDE + ac[i] * 16;
                *(uint4*)(aH + so) = pA[i];
                *(uint4*)(aL + so) = pA[4 + i];
            }
            {
                int so = brow * A_STRIDE + bc * 16;
                *(uint4*)(bH + so) = pB[0];
                *(uint4*)(bL + so) = pB[1];
            }
            if (c < 15) {
                int k0 = (c + 1) * 64;
                #pragma unroll
                for (int i = 0; i < 4; i++) {
                    size_t off = (size_t)arow[i] * Hq + k0 + ac[i] * 8;
                    pA[i]     = __ldcg((const uint4*)(hh + off));
                    pA[4 + i] = __ldcg((const uint4*)(hl + off));
                }
                pB[0] = *(const uint4*)(g_whi + bg + k0);
                pB[1] = *(const uint4*)(g_wlo + bg + k0);
            }
            __syncthreads();

            u32 oAh = buf * (2 * A_HALF);
            u32 oAl = oAh + A_HALF;
            u32 oBh = buf * (2 * B_HALF);
            u32 oBl = oBh + B_HALF;
            #pragma unroll
            for (int s = 0; s < 4; s++) {
                u32 ah[4], al[4], bh0[4], bh1[4], bl0[4], bl1[4];
                ldm4(ah[0], ah[1], ah[2], ah[3], aAddr + oAh + s * 32);
                ldm4(al[0], al[1], al[2], al[3], aAddr + oAl + s * 32);
                ldm4(bh0[0], bh0[1], bh0[2], bh0[3], bAddr + oBh + s * 32);
                ldm4(bh1[0], bh1[1], bh1[2], bh1[3], bAddr + oBh + s * 32 + 16);
                ldm4(bl0[0], bl0[1], bl0[2], bl0[3], bAddr + oBl + s * 32);
                ldm4(bl1[0], bl1[1], bl1[2], bl1[3], bAddr + oBl + s * 32 + 16);
                #pragma unroll
                for (int nt = 0; nt < 4; nt++) {
                    mma16816(acc[nt], ah, bh0[nt], bh1[nt]);
                    mma16816(acc[nt], ah, bl0[nt], bl1[nt]);
                    mma16816(acc[nt], al, bh0[nt], bh1[nt]);
                }
            }
            __syncthreads();
        }

        // ---- epilogue (registers only; c persistent) ----
        #pragma unroll
        for (int rr = 0; rr < 2; rr++) {
            int b = wid * 16 + g + rr * 8;
            const float* xr = g_xg + ((size_t)b * Tq + t) * G4 + n * NH + u0;
            float2 x0 = *(const float2*)(xr);
            float2 x1 = *(const float2*)(xr + Hq);
            float2 x2 = *(const float2*)(xr + 2 * Hq);
            float2 x3 = *(const float2*)(xr + 3 * Hq);

            float i0 = sigmoidf(acc[0][rr*2+0] + x0.x);
            float f0 = sigmoidf(acc[1][rr*2+0] + x1.x);
            float gg0 = tanhf(acc[2][rr*2+0] + x2.x);
            float o0 = sigmoidf(acc[3][rr*2+0] + x3.x);
            float i1 = sigmoidf(acc[0][rr*2+1] + x0.y);
            float f1 = sigmoidf(acc[1][rr*2+1] + x1.y);
            float gg1 = tanhf(acc[2][rr*2+1] + x2.y);
            float o1 = sigmoidf(acc[3][rr*2+1] + x3.y);

            float c0 = f0 * creg[rr*2+0] + i0 * gg0;
            float c1 = f1 * creg[rr*2+1] + i1 * gg1;
            creg[rr*2+0] = c0;
            creg[rr*2+1] = c1;
            float hx = o0 * tanhf(c0);
            float hy = o1 * tanhf(c1);

            size_t hob = (size_t)((t + 1) & 1) * (Bq * Hq) + (size_t)b * Hq + n * NH + u0;
            __nv_bfloat162 hi2, lo2;
            hi2.x = __float2bfloat16(hx);
            hi2.y = __float2bfloat16(hy);
            lo2.x = __float2bfloat16(hx - __bfloat162float(hi2.x));
            lo2.y = __float2bfloat16(hy - __bfloat162float(hi2.y));
            __stcg((unsigned int*)(g_hhi + hob), *(unsigned int*)&hi2);
            __stcg((unsigned int*)(g_hlo + hob), *(unsigned int*)&lo2);

            if (t == Tq - 1) {
                float2 hv; hv.x = hx; hv.y = hy;
                *(float2*)(g_hbuf + (size_t)b * Hq + n * NH + u0) = hv;
            }
        }

        // ---- global barrier between steps ----
        if (t < Tq - 1) {
            __threadfence();
            __syncthreads();
            if (tid == 0) {
                atomicAdd(&g_bar, 1u);
                unsigned int tgt = 128u * (t + 1);
                volatile unsigned int* p = &g_bar;
                while (*p < tgt) { }
                __threadfence();
            }
            __syncthreads();
        }
    }
}

// ---------------- fc1 ----------------
__global__ __launch_bounds__(256) void k_fc1(const float* __restrict__ fc1_w,
                                             const float* __restrict__ fc1_b) {
    int b = blockIdx.y;
    int f = blockIdx.x * 8 + (threadIdx.x >> 5);
    int lane = threadIdx.x & 31;
    const float* hr = g_hbuf + (size_t)b * Hq;
    const float* wr = fc1_w + (size_t)f * Hq;
    float s = 0.f;
    for (int k = lane; k < Hq; k += 32) s += hr[k] * wr[k];
    #pragma unroll
    for (int off = 16; off; off >>= 1) s += __shfl_xor_sync(0xffffffffu, s, off);
    if (lane == 0) g_h1[b * Fq + f] = s + fc1_b[f];
}

// ---------------- BN stats ----------------
__global__ void k_bn(const float* __restrict__ gamma, const float* __restrict__ beta) {
    int f = threadIdx.x;
    float s = 0.f, ss = 0.f;
    for (int b = 0; b < Bq; b++) { float v = g_h1[b * Fq + f]; s += v; ss += v * v; }
    float mu = s * (1.f / Bq);
    float var = ss * (1.f / Bq) - mu * mu;
    float rstd = rsqrtf(var + 1e-5f);
    float sc = rstd * gamma[f];
    g_s[f] = sc;
    g_t[f] = beta[f] - mu * sc;
}

// ---------------- fc2 ----------------
__global__ __launch_bounds__(320) void k_out(const float* __restrict__ fc2_w,
                                             const float* __restrict__ fc2_b,
                                             float* __restrict__ out) {
    int b = blockIdx.x;
    int o = threadIdx.x >> 5;
    int lane = threadIdx.x & 31;
    const float* h1r = g_h1 + (size_t)b * Fq;
    const float* wr = fc2_w + (size_t)o * Fq;
    float s = 0.f;
    for (int f = lane; f < Fq; f += 32) s += (h1r[f] * g_s[f] + g_t[f]) * wr[f];
    #pragma unroll
    for (int off = 16; off; off >>= 1) s += __shfl_xor_sync(0xffffffffu, s, off);
    if (lane == 0) out[b * Oq + o] = s + fc2_b[o];
}

// ---------------- launch ----------------
extern "C" void kernel_launch(void* const* d_in, const int* in_sizes, int n_in,
                              void* d_out, int out_size) {
    const int*   x     = (const int*)  d_in[0];
    const float* x_top = (const float*)d_in[1];
    const float* emb   = (const float*)d_in[2];
    const float* w_ih  = (const float*)d_in[3];
    const float* w_hh  = (const float*)d_in[4];
    const float* w_th  = (const float*)d_in[5];
    const float* bias  = (const float*)d_in[6];
    const float* fc1_w = (const float*)d_in[7];
    const float* fc1_b = (const float*)d_in[8];
    const float* gamma = (const float*)d_in[9];
    const float* beta  = (const float*)d_in[10];
    const float* fc2_w = (const float*)d_in[11];
    const float* fc2_b = (const float*)d_in[12];
    float* out = (float*)d_out;

    cudaFuncSetAttribute(k_xg_t, cudaFuncAttributeMaxDynamicSharedMemorySize, XG_SMEM);
    cudaFuncSetAttribute(k_rnn,  cudaFuncAttributeMaxDynamicSharedMemorySize, STEP_SMEM);

    k_init<<<(Bq * Hq + 255) / 256, 256>>>();
    k_wsplit<<<(G4 * Hq / 4) / 256, 256>>>(w_hh);
    k_wihb<<<(G4 * Eq / 4) / 256, 256>>>(w_ih);
    k_xeb<<<(Bq * Tq * Eq / 4) / 256, 256>>>(x, emb);
    k_topic<<<Bq, 256>>>(x_top, w_th, bias);
    dim3 gxg(G4 / 64, (Bq * Tq) / 128);
    k_xg_t<<<gxg, 256, XG_SMEM>>>();
    k_rnn<<<128, 256, STEP_SMEM>>>();
    k_fc1<<<dim3(Fq / 8, Bq), 256>>>(fc1_w, fc1_b);
    k_bn<<<1, Fq>>>(gamma, beta);
    k_out<<<Bq, 320>>>(fc2_w, fc2_b, out);
}

// round 5
// speedup vs baseline: 2.8115x; 1.0982x over previous
#include <cuda_runtime.h>
#include <cuda_bf16.h>
#include <math.h>
#include <cstdint>

#define Bq   128
#define Tq   256
#define Eq   512
#define Hq   1024
#define TOPq 128
#define Fq   512
#define Oq   10
#define G4   4096
#define NH   8

typedef unsigned long long u64;
typedef unsigned int u32;

// ---------------- device scratch ----------------
__device__ float g_xg[(size_t)Bq * Tq * G4];
__device__ float g_tb[Bq * G4];
__device__ float g_hbuf[Bq * Hq];
__device__ __nv_bfloat16 g_hhi[2 * Bq * Hq];
__device__ __nv_bfloat16 g_hlo[2 * Bq * Hq];
__device__ __nv_bfloat16 g_whi[(size_t)G4 * Hq];
__device__ __nv_bfloat16 g_wlo[(size_t)G4 * Hq];
__device__ __nv_bfloat16 g_xeb[(size_t)Bq * Tq * Eq];
__device__ __nv_bfloat16 g_wihb[(size_t)G4 * Eq];
__device__ float g_h1[Bq * Fq];
__device__ float g_s[Fq];
__device__ float g_t[Fq];
__device__ unsigned int g_bar;

// ---------------- helpers ----------------
__device__ __forceinline__ float sigmoidf(float x) { return 1.0f / (1.0f + expf(-x)); }

__device__ __forceinline__ u32 smem_u32(const void* p) {
    u32 a; asm("{ .reg .u64 t; cvta.to.shared.u64 t, %1; cvt.u32.u64 %0, t; }" : "=r"(a) : "l"(p));
    return a;
}
__device__ __forceinline__ void ldm4(u32 &r0, u32 &r1, u32 &r2, u32 &r3, u32 addr) {
    asm volatile("ldmatrix.sync.aligned.m8n8.x4.shared.b16 {%0,%1,%2,%3}, [%4];"
        : "=r"(r0), "=r"(r1), "=r"(r2), "=r"(r3) : "r"(addr));
}
__device__ __forceinline__ void mma16816(float* d, const u32* a, u32 b0, u32 b1) {
    asm volatile("mma.sync.aligned.m16n8k16.row.col.f32.bf16.bf16.f32 "
        "{%0,%1,%2,%3}, {%4,%5,%6,%7}, {%8,%9}, {%0,%1,%2,%3};"
        : "+f"(d[0]), "+f"(d[1]), "+f"(d[2]), "+f"(d[3])
        : "r"(a[0]), "r"(a[1]), "r"(a[2]), "r"(a[3]), "r"(b0), "r"(b1));
}
__device__ __forceinline__ void cpa16(u32 dst, const void* src) {
    asm volatile("cp.async.cg.shared.global [%0], [%1], 16;" :: "r"(dst), "l"(src));
}
#define CP_COMMIT() asm volatile("cp.async.commit_group;" ::: "memory")
#define CP_WAIT0()  asm volatile("cp.async.wait_group 0;" ::: "memory")

// ---------------- init ----------------
__global__ void k_init() {
    int i = blockIdx.x * blockDim.x + threadIdx.x;
    if (i == 0) g_bar = 0u;
    if (i < Bq * Hq) {
        g_hhi[i] = __float2bfloat16(0.f);
        g_hlo[i] = __float2bfloat16(0.f);
    }
}

// ---------------- split w_hh into bf16 hi/lo ----------------
__global__ __launch_bounds__(256) void k_wsplit(const float* __restrict__ w) {
    size_t i = ((size_t)blockIdx.x * 256 + threadIdx.x) * 4;
    float4 v = *(const float4*)(w + i);
    float vv[4] = {v.x, v.y, v.z, v.w};
    __nv_bfloat16 hi[4], lo[4];
    #pragma unroll
    for (int j = 0; j < 4; j++) {
        hi[j] = __float2bfloat16(vv[j]);
        lo[j] = __float2bfloat16(vv[j] - __bfloat162float(hi[j]));
    }
    *(uint2*)(g_whi + i) = *(uint2*)hi;
    *(uint2*)(g_wlo + i) = *(uint2*)lo;
}

// ---------------- w_ih -> bf16 ----------------
__global__ __launch_bounds__(256) void k_wihb(const float* __restrict__ w) {
    size_t i = ((size_t)blockIdx.x * 256 + threadIdx.x) * 4;
    float4 v = *(const float4*)(w + i);
    __nv_bfloat16 b[4] = {__float2bfloat16(v.x), __float2bfloat16(v.y),
                          __float2bfloat16(v.z), __float2bfloat16(v.w)};
    *(uint2*)(g_wihb + i) = *(uint2*)b;
}

// ---------------- emb gather -> bf16 ----------------
__global__ __launch_bounds__(256) void k_xeb(const int* __restrict__ x,
                                             const float* __restrict__ emb) {
    size_t idx = (size_t)blockIdx.x * 256 + threadIdx.x;
    int m = (int)(idx >> 7);
    int e4 = ((int)idx & 127) * 4;
    int row = x[m];
    float4 v = *(const float4*)(emb + (size_t)row * Eq + e4);
    __nv_bfloat16 b[4] = {__float2bfloat16(v.x), __float2bfloat16(v.y),
                          __float2bfloat16(v.z), __float2bfloat16(v.w)};
    *(uint2*)(g_xeb + (size_t)m * Eq + e4) = *(uint2*)b;
}

// ---------------- topic bias ----------------
__global__ __launch_bounds__(256) void k_topic(const float* __restrict__ x_top,
                                               const float* __restrict__ w_th,
                                               const float* __restrict__ bias) {
    __shared__ float xt[TOPq];
    int b = blockIdx.x, tid = threadIdx.x;
    if (tid < TOPq) xt[tid] = x_top[b * TOPq + tid];
    __syncthreads();
    for (int g = tid; g < G4; g += 256) {
        const float4* wr = (const float4*)(w_th + (size_t)g * TOPq);
        float s = bias[g];
        #pragma unroll
        for (int k = 0; k < TOPq / 4; k++) {
            float4 w4 = wr[k];
            s += xt[4*k]*w4.x + xt[4*k+1]*w4.y + xt[4*k+2]*w4.z + xt[4*k+3]*w4.w;
        }
        g_tb[b * G4 + g] = s;
    }
}

// ---------------- xg GEMM: single-pass bf16 tensor, cp.async pipeline ------
#define XA_STRIDE 144
#define XA_HALF   18432
#define XB_BASE   36864
#define XB_HALF   9216
#define XG_SMEM   55296

__global__ __launch_bounds__(256) void k_xg_t() {
    extern __shared__ char dsm[];
    int tid = threadIdx.x, wid = tid >> 5, lane = tid & 31;
    int n0 = blockIdx.x * 64;
    int m0 = blockIdx.y * 128;

    int arow[4], ac[4];
    #pragma unroll
    for (int i = 0; i < 4; i++) { int u = tid + i * 256; arow[i] = u >> 3; ac[i] = u & 7; }
    int brow[2], bc[2];
    #pragma unroll
    for (int i = 0; i < 2; i++) { int u = tid + i * 256; brow[i] = u >> 3; bc[i] = u & 7; }

    u32 sb = smem_u32(dsm);
    int amrow = wid * 16 + (lane & 7) + ((lane >> 3) & 1) * 8;
    u32 aAddr = sb + amrow * XA_STRIDE + (lane >> 4) * 16;
    u32 bAddr = sb + XB_BASE + lane * XA_STRIDE;

    float acc[8][4];
    #pragma unroll
    for (int i = 0; i < 8; i++) { acc[i][0]=0.f; acc[i][1]=0.f; acc[i][2]=0.f; acc[i][3]=0.f; }

    const __nv_bfloat16* Ag = g_xeb + (size_t)m0 * Eq;
    const __nv_bfloat16* Bg = g_wihb + (size_t)n0 * Eq;

    // issue chunk 0
    {
        u32 aS = sb, bS = sb + XB_BASE;
        #pragma unroll
        for (int i = 0; i < 4; i++)
            cpa16(aS + arow[i] * XA_STRIDE + ac[i] * 16, Ag + (size_t)arow[i] * Eq + ac[i] * 8);
        #pragma unroll
        for (int i = 0; i < 2; i++)
            cpa16(bS + brow[i] * XA_STRIDE + bc[i] * 16, Bg + (size_t)brow[i] * Eq + bc[i] * 8);
        CP_COMMIT();
    }

    for (int c = 0; c < 8; c++) {
        int buf = c & 1;
        CP_WAIT0();
        __syncthreads();
        if (c < 7) {
            int k0 = (c + 1) * 64;
            u32 aS = sb + (buf ^ 1) * XA_HALF;
            u32 bS = sb + XB_BASE + (buf ^ 1) * XB_HALF;
            #pragma unroll
            for (int i = 0; i < 4; i++)
                cpa16(aS + arow[i] * XA_STRIDE + ac[i] * 16, Ag + (size_t)arow[i] * Eq + k0 + ac[i] * 8);
            #pragma unroll
            for (int i = 0; i < 2; i++)
                cpa16(bS + brow[i] * XA_STRIDE + bc[i] * 16, Bg + (size_t)brow[i] * Eq + k0 + bc[i] * 8);
            CP_COMMIT();
        }

        u32 oA = buf * XA_HALF, oB = buf * XB_HALF;
        #pragma unroll
        for (int s = 0; s < 4; s++) {
            u32 a[4], b0[4], b1[4], b2[4], b3[4];
            ldm4(a[0], a[1], a[2], a[3], aAddr + oA + s * 32);
            ldm4(b0[0], b0[1], b0[2], b0[3], bAddr + oB + s * 32);
            ldm4(b1[0], b1[1], b1[2], b1[3], bAddr + oB + s * 32 + 16);
            ldm4(b2[0], b2[1], b2[2], b2[3], bAddr + 4608 + oB + s * 32);
            ldm4(b3[0], b3[1], b3[2], b3[3], bAddr + 4608 + oB + s * 32 + 16);
            #pragma unroll
            for (int nt = 0; nt < 4; nt++) mma16816(acc[nt], a, b0[nt], b1[nt]);
            #pragma unroll
            for (int nt = 0; nt < 4; nt++) mma16816(acc[4 + nt], a, b2[nt], b3[nt]);
        }
    }

    int g = lane >> 2, tq = lane & 3;
    int bb = m0 >> 8;
    const float* tbr = g_tb + (size_t)bb * G4 + n0;
    #pragma unroll
    for (int rr = 0; rr < 2; rr++) {
        int m = m0 + wid * 16 + g + rr * 8;
        float* orow = g_xg + (size_t)m * G4 + n0;
        #pragma unroll
        for (int nt = 0; nt < 8; nt++) {
            int nn = nt * 8 + tq * 2;
            float2 tb2 = *(const float2*)(tbr + nn);
            float2 o;
            o.x = acc[nt][rr * 2 + 0] + tb2.x;
            o.y = acc[nt][rr * 2 + 1] + tb2.y;
            *(float2*)(orow + nn) = o;
        }
    }
}

// ---------------- persistent LSTM recurrence ----------------
// Smem: A double-buffer 2 x (hi 18432 + lo 18432) = 73728
//       B persistent: 16 chunks x (hi 4608 + lo 4608) = 147456  -> total 221184
#define A_STRIDE 144
#define A_BUF    36864
#define A_LO     18432
#define BP_BASE  73728
#define BP_CHUNK 9216
#define RNN_SMEM 221184

__global__ __launch_bounds__(256) void k_rnn() {
    extern __shared__ char dsm[];
    int tid = threadIdx.x, wid = tid >> 5, lane = tid & 31;
    int n = blockIdx.x;
    u32 sb = smem_u32(dsm);

    int arow[4], ac[4];
    #pragma unroll
    for (int i = 0; i < 4; i++) { int u = tid + i * 256; arow[i] = u >> 3; ac[i] = u & 7; }

    // ---- load persistent B (w_hh slice) into smem: 32 rows x 1024 k, hi+lo ----
    {
        int brow = tid >> 3, bc = tid & 7;
        size_t bg = (size_t)((brow >> 3) * Hq + n * NH + (brow & 7)) * Hq + bc * 8;
        u32 dst = sb + BP_BASE + brow * A_STRIDE + bc * 16;
        #pragma unroll
        for (int c = 0; c < 16; c++) {
            cpa16(dst + c * BP_CHUNK,        g_whi + bg + c * 64);
            cpa16(dst + c * BP_CHUNK + 4608, g_wlo + bg + c * 64);
        }
        CP_COMMIT();
    }

    int amrow = wid * 16 + (lane & 7) + ((lane >> 3) & 1) * 8;
    u32 aAddr = sb + amrow * A_STRIDE + (lane >> 4) * 16;
    u32 bAddr = sb + BP_BASE + lane * A_STRIDE;

    int g = lane >> 2, tq = lane & 3;
    int u0 = tq * 3;  // placeholder, fixed below
    u0 = tq * 2;
    float creg[4] = {0.f, 0.f, 0.f, 0.f};

    CP_WAIT0();
    __syncthreads();

    for (int t = 0; t < Tq; t++) {
        const __nv_bfloat16* hh = g_hhi + (size_t)(t & 1) * (Bq * Hq);
        const __nv_bfloat16* hl = g_hlo + (size_t)(t & 1) * (Bq * Hq);

        float acc[4][4];
        #pragma unroll
        for (int i = 0; i < 4; i++) { acc[i][0]=0.f; acc[i][1]=0.f; acc[i][2]=0.f; acc[i][3]=0.f; }

        // issue A chunk 0 into buf 0
        {
            u32 aH = sb, aL = sb + A_LO;
            #pragma unroll
            for (int i = 0; i < 4; i++) {
                size_t off = (size_t)arow[i] * Hq + ac[i] * 8;
                u32 so = arow[i] * A_STRIDE + ac[i] * 16;
                cpa16(aH + so, hh + off);
                cpa16(aL + so, hl + off);
            }
            CP_COMMIT();
        }

        for (int c = 0; c < 16; c++) {
            int buf = c & 1;
            CP_WAIT0();
            __syncthreads();
            if (c < 15) {
                int k0 = (c + 1) * 64;
                u32 aH = sb + (buf ^ 1) * A_BUF, aL = aH + A_LO;
                #pragma unroll
                for (int i = 0; i < 4; i++) {
                    size_t off = (size_t)arow[i] * Hq + k0 + ac[i] * 8;
                    u32 so = arow[i] * A_STRIDE + ac[i] * 16;
                    cpa16(aH + so, hh + off);
                    cpa16(aL + so, hl + off);
                }
                CP_COMMIT();
            }

            u32 oAh = buf * A_BUF;
            u32 oAl = oAh + A_LO;
            u32 oB = c * BP_CHUNK;
            #pragma unroll
            for (int s = 0; s < 4; s++) {
                u32 ah[4], al[4], bh0[4], bh1[4], bl0[4], bl1[4];
                ldm4(ah[0], ah[1], ah[2], ah[3], aAddr + oAh + s * 32);
                ldm4(al[0], al[1], al[2], al[3], aAddr + oAl + s * 32);
                ldm4(bh0[0], bh0[1], bh0[2], bh0[3], bAddr + oB + s * 32);
                ldm4(bh1[0], bh1[1], bh1[2], bh1[3], bAddr + oB + s * 32 + 16);
                ldm4(bl0[0], bl0[1], bl0[2], bl0[3], bAddr + oB + 4608 + s * 32);
                ldm4(bl1[0], bl1[1], bl1[2], bl1[3], bAddr + oB + 4608 + s * 32 + 16);
                #pragma unroll
                for (int nt = 0; nt < 4; nt++) {
                    mma16816(acc[nt], ah, bh0[nt], bh1[nt]);
                    mma16816(acc[nt], ah, bl0[nt], bl1[nt]);
                    mma16816(acc[nt], al, bh0[nt], bh1[nt]);
                }
            }
        }

        // ---- epilogue (registers only; c persistent) ----
        #pragma unroll
        for (int rr = 0; rr < 2; rr++) {
            int b = wid * 16 + g + rr * 8;
            const float* xr = g_xg + ((size_t)b * Tq + t) * G4 + n * NH + u0;
            float2 x0 = *(const float2*)(xr);
            float2 x1 = *(const float2*)(xr + Hq);
            float2 x2 = *(const float2*)(xr + 2 * Hq);
            float2 x3 = *(const float2*)(xr + 3 * Hq);

            float i0 = sigmoidf(acc[0][rr*2+0] + x0.x);
            float f0 = sigmoidf(acc[1][rr*2+0] + x1.x);
            float gg0 = tanhf(acc[2][rr*2+0] + x2.x);
            float o0 = sigmoidf(acc[3][rr*2+0] + x3.x);
            float i1 = sigmoidf(acc[0][rr*2+1] + x0.y);
            float f1 = sigmoidf(acc[1][rr*2+1] + x1.y);
            float gg1 = tanhf(acc[2][rr*2+1] + x2.y);
            float o1 = sigmoidf(acc[3][rr*2+1] + x3.y);

            float c0 = f0 * creg[rr*2+0] + i0 * gg0;
            float c1 = f1 * creg[rr*2+1] + i1 * gg1;
            creg[rr*2+0] = c0;
            creg[rr*2+1] = c1;
            float hx = o0 * tanhf(c0);
            float hy = o1 * tanhf(c1);

            size_t hob = (size_t)((t + 1) & 1) * (Bq * Hq) + (size_t)b * Hq + n * NH + u0;
            __nv_bfloat162 hi2, lo2;
            hi2.x = __float2bfloat16(hx);
            hi2.y = __float2bfloat16(hy);
            lo2.x = __float2bfloat16(hx - __bfloat162float(hi2.x));
            lo2.y = __float2bfloat16(hy - __bfloat162float(hi2.y));
            __stcg((unsigned int*)(g_hhi + hob), *(unsigned int*)&hi2);
            __stcg((unsigned int*)(g_hlo + hob), *(unsigned int*)&lo2);

            if (t == Tq - 1) {
                float2 hv; hv.x = hx; hv.y = hy;
                *(float2*)(g_hbuf + (size_t)b * Hq + n * NH + u0) = hv;
            }
        }

        // ---- global barrier between steps ----
        if (t < Tq - 1) {
            __threadfence();
            __syncthreads();
            if (tid == 0) {
                atomicAdd(&g_bar, 1u);
                unsigned int tgt = 128u * (t + 1);
                volatile unsigned int* p = &g_bar;
                while (*p < tgt) { }
                __threadfence();
            }
            __syncthreads();
        }
    }
}

// ---------------- fc1 ----------------
__global__ __launch_bounds__(256) void k_fc1(const float* __restrict__ fc1_w,
                                             const float* __restrict__ fc1_b) {
    int b = blockIdx.y;
    int f = blockIdx.x * 8 + (threadIdx.x >> 5);
    int lane = threadIdx.x & 31;
    const float* hr = g_hbuf + (size_t)b * Hq;
    const float* wr = fc1_w + (size_t)f * Hq;
    float s = 0.f;
    for (int k = lane; k < Hq; k += 32) s += hr[k] * wr[k];
    #pragma unroll
    for (int off = 16; off; off >>= 1) s += __shfl_xor_sync(0xffffffffu, s, off);
    if (lane == 0) g_h1[b * Fq + f] = s + fc1_b[f];
}

// ---------------- BN stats ----------------
__global__ void k_bn(const float* __restrict__ gamma, const float* __restrict__ beta) {
    int f = threadIdx.x;
    float s = 0.f, ss = 0.f;
    for (int b = 0; b < Bq; b++) { float v = g_h1[b * Fq + f]; s += v; ss += v * v; }
    float mu = s * (1.f / Bq);
    float var = ss * (1.f / Bq) - mu * mu;
    float rstd = rsqrtf(var + 1e-5f);
    float sc = rstd * gamma[f];
    g_s[f] = sc;
    g_t[f] = beta[f] - mu * sc;
}

// ---------------- fc2 ----------------
__global__ __launch_bounds__(320) void k_out(const float* __restrict__ fc2_w,
                                             const float* __restrict__ fc2_b,
                                             float* __restrict__ out) {
    int b = blockIdx.x;
    int o = threadIdx.x >> 5;
    int lane = threadIdx.x & 31;
    const float* h1r = g_h1 + (size_t)b * Fq;
    const float* wr = fc2_w + (size_t)o * Fq;
    float s = 0.f;
    for (int f = lane; f < Fq; f += 32) s += (h1r[f] * g_s[f] + g_t[f]) * wr[f];
    #pragma unroll
    for (int off = 16; off; off >>= 1) s += __shfl_xor_sync(0xffffffffu, s, off);
    if (lane == 0) out[b * Oq + o] = s + fc2_b[o];
}

// ---------------- launch ----------------
extern "C" void kernel_launch(void* const* d_in, const int* in_sizes, int n_in,
                              void* d_out, int out_size) {
    const int*   x     = (const int*)  d_in[0];
    const float* x_top = (const float*)d_in[1];
    const float* emb   = (const float*)d_in[2];
    const float* w_ih  = (const float*)d_in[3];
    const float* w_hh  = (const float*)d_in[4];
    const float* w_th  = (const float*)d_in[5];
    const float* bias  = (const float*)d_in[6];
    const float* fc1_w = (const float*)d_in[7];
    const float* fc1_b = (const float*)d_in[8];
    const float* gamma = (const float*)d_in[9];
    const float* beta  = (const float*)d_in[10];
    const float* fc2_w = (const float*)d_in[11];
    const float* fc2_b = (const float*)d_in[12];
    float* out = (float*)d_out;

    cudaFuncSetAttribute(k_xg_t, cudaFuncAttributeMaxDynamicSharedMemorySize, XG_SMEM);
    cudaFuncSetAttribute(k_rnn,  cudaFuncAttributeMaxDynamicSharedMemorySize, RNN_SMEM);

    k_init<<<(Bq * Hq + 255) / 256, 256>>>();
    k_wsplit<<<(G4 * Hq / 4) / 256, 256>>>(w_hh);
    k_wihb<<<(G4 * Eq / 4) / 256, 256>>>(w_ih);
    k_xeb<<<(Bq * Tq * Eq / 4) / 256, 256>>>(x, emb);
    k_topic<<<Bq, 256>>>(x_top, w_th, bias);
    dim3 gxg(G4 / 64, (Bq * Tq) / 128);
    k_xg_t<<<gxg, 256, XG_SMEM>>>();
    k_rnn<<<128, 256, RNN_SMEM>>>();
    k_fc1<<<dim3(Fq / 8, Bq), 256>>>(fc1_w, fc1_b);
    k_bn<<<1, Fq>>>(gamma, beta);
    k_out<<<Bq, 320>>>(fc2_w, fc2_b, out);
}